// round 4
// baseline (speedup 1.0000x reference)
#include <cuda_runtime.h>
#include <cstdint>

#define BB 4
#define NPTS 20000
#define CC 512
#define MM 1024
#define GRASP_TH 0.1f

#define CLUSTER 8
#define FPS_T 256
#define FPS_W (FPS_T / 32)            // 8 warps
#define CAPR 4
#define REGN_CTA (FPS_T * CAPR)       // 1024 pts per CTA in registers
#define REGN_TOT (CLUSTER * REGN_CTA) // 8192
#define ENT (CLUSTER * FPS_W)         // 64 exchange entries

// ---------------- scratch (static device allocations; no cudaMalloc) -------
__device__ float4 g_cp[BB * NPTS];    // compacted xyz
__device__ int    g_cidx[BB * NPTS];  // compacted -> original index
__device__ float  g_mind[BB * NPTS];  // FPS min-dist (gmem fallback region only)
__device__ int    g_fps[BB * MM];     // sampled original indices
__device__ int    g_nn[BB * MM * 3];  // 3-NN indices
__device__ float  g_w[BB * MM * 3];   // normalized IDW weights
__device__ float4 g_pc4[BB * NPTS];   // full cloud packed as float4

__device__ __forceinline__ float finf()  { return __int_as_float(0x7f800000); }
__device__ __forceinline__ float fnegz() { return __int_as_float(0x80000000); }

__device__ __forceinline__ unsigned smem_u32(const void* p) {
    return (unsigned)__cvta_generic_to_shared(p);
}
__device__ __forceinline__ unsigned mapa_u32(unsigned a, unsigned r) {
    unsigned o;
    asm("mapa.shared::cluster.u32 %0, %1, %2;" : "=r"(o) : "r"(a), "r"(r));
    return o;
}
__device__ __forceinline__ void st_cl64(unsigned a, unsigned long long v) {
    asm volatile("st.shared::cluster.b64 [%0], %1;" :: "r"(a), "l"(v) : "memory");
}
__device__ __forceinline__ void st_cl32(unsigned a, unsigned v) {
    asm volatile("st.shared::cluster.b32 [%0], %1;" :: "r"(a), "r"(v) : "memory");
}
__device__ __forceinline__ void mbar_init(unsigned a, unsigned c) {
    asm volatile("mbarrier.init.shared.b64 [%0], %1;" :: "r"(a), "r"(c) : "memory");
}
__device__ __forceinline__ void mbar_arrive_rel_cluster(unsigned a) {
    asm volatile("mbarrier.arrive.release.cluster.shared::cluster.b64 _, [%0];"
                 :: "r"(a) : "memory");
}
__device__ __forceinline__ void mbar_wait_acq_cluster(unsigned a, unsigned parity) {
    asm volatile("{\n\t"
                 ".reg .pred P;\n"
                 "WLP%=:\n\t"
                 "mbarrier.try_wait.parity.acquire.cluster.shared::cta.b64 P, [%0], %1;\n\t"
                 "@!P bra WLP%=;\n\t"
                 "}"
                 :: "r"(a), "r"(parity) : "memory");
}
__device__ __forceinline__ void cluster_sync_() {
    asm volatile("barrier.cluster.arrive.aligned;" ::: "memory");
    asm volatile("barrier.cluster.wait.aligned;" ::: "memory");
}

// ============================================================================
// Kernel 0: pack full cloud into float4 for LDS.128 in nn_kernel
// ============================================================================
__global__ __launch_bounds__(256)
void pack_kernel(const float* __restrict__ pc)
{
    int e = blockIdx.x * 256 + threadIdx.x;
    if (e < BB * NPTS) {
        const float* p = pc + (size_t)e * 3;
        g_pc4[e] = make_float4(p[0], p[1], p[2], 0.0f);
    }
}

// ============================================================================
// Kernel 1: masked FPS, cluster-parallel. 8 CTAs per batch (one cluster),
// register-resident point state, cross-CTA argmax via DSMEM all-to-all +
// mbarrier (release/acquire at cluster scope), one barrier per iteration.
// Distance bit-exact vs XLA: no FMA, ((dx*dx + dy*dy) + dz*dz); argmax =
// max value, lowest original index (compaction is order-preserving).
// ============================================================================
__global__ __launch_bounds__(FPS_T, 1) __cluster_dims__(CLUSTER, 1, 1)
void fps_kernel(const float* __restrict__ pc,
                const float* __restrict__ obj,
                const float* __restrict__ gr)
{
    const int b    = blockIdx.x / CLUSTER;
    const int tid  = threadIdx.x;
    const int lane = tid & 31;
    const int wid  = tid >> 5;
    unsigned rank;
    asm("mov.u32 %0, %%cluster_ctarank;" : "=r"(rank));

    __shared__ int s_wsum[FPS_W];
    __shared__ int s_base;
    __shared__ unsigned long long s_vi[2][ENT];   // (value<<32) | ~compacted_idx
    __shared__ unsigned long long s_xy[2][ENT];
    __shared__ float              s_z[2][ENT];
    __shared__ unsigned long long s_mbar;

    if (tid == 0) {
        s_base = 0;
        mbar_init(smem_u32(&s_mbar), ENT);        // 64 arrivals per phase
    }
    __syncthreads();

    const float* objb = obj + (size_t)b * 2 * NPTS;
    const float* grb  = gr  + (size_t)b * NPTS;
    const float* pcb  = pc  + (size_t)b * NPTS * 3;

    // ---- order-preserving compaction (redundant in each CTA of cluster) ----
    for (int start = 0; start < NPTS; start += FPS_T) {
        int i = start + tid;
        bool p = false;
        if (i < NPTS)
            p = (objb[NPTS + i] > objb[i]) && (grb[i] > GRASP_TH);
        unsigned bal = __ballot_sync(0xffffffffu, p);
        int wcnt = __popc(bal);
        int wpre = __popc(bal & ((1u << lane) - 1u));
        if (lane == 0) s_wsum[wid] = wcnt;
        __syncthreads();
        if (tid == 0) {
            int acc = s_base;
            #pragma unroll
            for (int w = 0; w < FPS_W; ++w) { int c = s_wsum[w]; s_wsum[w] = acc; acc += c; }
            s_base = acc;
        }
        __syncthreads();
        if (p) {
            int pos = s_wsum[wid] + wpre;
            g_cidx[b * NPTS + pos] = i;
            float4 q;
            q.x = pcb[3 * i]; q.y = pcb[3 * i + 1]; q.z = pcb[3 * i + 2]; q.w = 0.0f;
            g_cp[b * NPTS + pos] = q;
        }
        __syncthreads();
    }
    const int cnt = s_base;

    // mbarrier init must be cluster-visible before first arrive
    cluster_sync_();

    if (cnt == 0) {
        if (rank == 0)
            for (int j = tid; j < MM; j += FPS_T) g_fps[b * MM + j] = 0;
        return;
    }

    const float4* cp = g_cp + b * NPTS;

    // ---- per-CTA partition + register load ----
    const int chunk = min(REGN_CTA, (cnt + CLUSTER - 1) / CLUSTER);
    const int lo    = (int)rank * chunk;
    const int myn   = max(0, min(chunk, cnt - lo));

    float rx[CAPR], ry[CAPR], rz[CAPR], md[CAPR];
    #pragma unroll
    for (int k = 0; k < CAPR; ++k) {
        int o = tid + k * FPS_T;
        if (o < myn) {
            float4 q = cp[lo + o];
            rx[k] = q.x; ry[k] = q.y; rz[k] = q.z;
            md[k] = finf();
        } else {
            rx[k] = 0.0f; ry[k] = 0.0f; rz[k] = 0.0f;
            md[k] = fnegz();         // -0.0: never beats bV (>= +0.0) under strict >
        }
    }

    // fallback (cnt > 8192): gmem state, disjoint ownership across cluster
    float* gmind = g_mind + b * NPTS;
    const int gtid = (int)rank * FPS_T + tid;
    for (int i = REGN_TOT + gtid; i < cnt; i += CLUSTER * FPS_T) gmind[i] = finf();

    // ---- first pick = compacted point 0 ----
    float4 p0 = cp[0];
    float lx = p0.x, ly = p0.y, lz = p0.z;
    if (rank == 0 && tid == 0) g_fps[b * MM] = g_cidx[b * NPTS];

    const unsigned a_vi_base = smem_u32(&s_vi[0][0]);
    const unsigned d_xy = smem_u32(&s_xy[0][0]) - a_vi_base;
    const unsigned d_z  = smem_u32(&s_z[0][0])  - a_vi_base;
    const unsigned a_mb = smem_u32(&s_mbar);
    const int src = (int)rank * FPS_W + wid;      // my entry id (0..63)

    for (int it = 1; it < MM; ++it) {
        const unsigned ph = (unsigned)(it - 1) & 1u;

        // --- update owned minds, track per-lane best (strict > keeps lowest idx) ---
        float    bV = 0.0f;
        unsigned bI = 0xffffffffu;
        float    bX = 0.0f, bY = 0.0f, bZ = 0.0f;
        #pragma unroll
        for (int k = 0; k < CAPR; ++k) {
            if (k * FPS_T < myn) {                 // uniform per-CTA branch
                float dx = rx[k] - lx;
                float dy = ry[k] - ly;
                float dz = rz[k] - lz;
                // bit-exact vs XLA: ((dx*dx + dy*dy) + dz*dz), no contraction
                float d = __fadd_rn(__fadd_rn(__fmul_rn(dx, dx),
                                              __fmul_rn(dy, dy)),
                                    __fmul_rn(dz, dz));
                float m = fminf(md[k], d);
                md[k] = m;
                if (m > bV) { bV = m; bI = (unsigned)(lo + tid + k * FPS_T);
                              bX = rx[k]; bY = ry[k]; bZ = rz[k]; }
            }
        }
        for (int i = REGN_TOT + gtid; i < cnt; i += CLUSTER * FPS_T) {
            float4 q = cp[i];
            float dx = q.x - lx;
            float dy = q.y - ly;
            float dz = q.z - lz;
            float d = __fadd_rn(__fadd_rn(__fmul_rn(dx, dx),
                                          __fmul_rn(dy, dy)),
                                __fmul_rn(dz, dz));
            float m = fminf(gmind[i], d);
            gmind[i] = m;
            if (m > bV || (m == bV && (unsigned)i < bI)) {
                bV = m; bI = (unsigned)i; bX = q.x; bY = q.y; bZ = q.z;
            }
        }

        // --- warp argmax (max value, min index) via REDUX on bits ---
        unsigned vb = __float_as_uint(bV);
        unsigned wv = __reduce_max_sync(0xffffffffu, vb);
        unsigned cand = (vb == wv) ? bI : 0xffffffffu;
        unsigned wi = __reduce_min_sync(0xffffffffu, cand);
        unsigned wb = __ballot_sync(0xffffffffu, (vb == wv) & (bI == wi));

        // --- elected lane broadcasts warp winner to all cluster CTAs ---
        if (lane == __ffs(wb) - 1) {
            unsigned long long vi = ((unsigned long long)wv << 32) | (unsigned)(~wi);
            unsigned long long xy = ((unsigned long long)__float_as_uint(bY) << 32)
                                    | __float_as_uint(bX);
            unsigned a_local = a_vi_base + (ph * ENT + (unsigned)src) * 8u;
            unsigned zoff    = d_z  + (ph * ENT + (unsigned)src) * 4u - (ph * ENT + (unsigned)src) * 8u;
            #pragma unroll
            for (unsigned r = 0; r < CLUSTER; ++r) {
                unsigned ra = mapa_u32(a_local, r);
                st_cl64(ra, vi);
                st_cl64(ra + d_xy, xy);
                st_cl32(ra + zoff, __float_as_uint(bZ));
            }
            #pragma unroll
            for (unsigned r = 0; r < CLUSTER; ++r)
                mbar_arrive_rel_cluster(mapa_u32(a_mb, r));
        }

        // --- wait for all 64 warp-winners cluster-wide ---
        mbar_wait_acq_cluster(a_mb, ph);

        // --- final 64-entry argmax, redundantly in every warp ---
        unsigned long long e0 = s_vi[ph][lane];
        unsigned long long e1 = s_vi[ph][lane + 32];
        unsigned long long x0 = s_xy[ph][lane];
        unsigned long long x1 = s_xy[ph][lane + 32];
        float z0 = s_z[ph][lane];
        float z1 = s_z[ph][lane + 32];
        bool t = e1 > e0;
        unsigned long long e  = t ? e1 : e0;
        unsigned long long xy = t ? x1 : x0;
        float zz = t ? z1 : z0;
        unsigned hv = (unsigned)(e >> 32);
        unsigned lv = (unsigned)e;                 // = ~idx
        unsigned gv = __reduce_max_sync(0xffffffffu, hv);
        unsigned cl = (hv == gv) ? lv : 0u;        // max ~idx == min idx
        unsigned gl = __reduce_max_sync(0xffffffffu, cl);
        unsigned wb2 = __ballot_sync(0xffffffffu, (hv == gv) & (lv == gl));
        int ls = __ffs(wb2) - 1;
        unsigned gi = ~gl;
        lx = __uint_as_float(__shfl_sync(0xffffffffu, (unsigned)xy, ls));
        ly = __uint_as_float(__shfl_sync(0xffffffffu, (unsigned)(xy >> 32), ls));
        lz = __shfl_sync(0xffffffffu, zz, ls);
        if (gv == 0u) {                            // degenerate: all minds zero
            gi = 0u;
            float4 q = cp[0];
            lx = q.x; ly = q.y; lz = q.z;
        }

        if (rank == 0 && tid == 0)
            g_fps[b * MM + it] = g_cidx[b * NPTS + (int)gi];
    }
}

// ============================================================================
// Kernel 2: three_nn — tiled brute force over float4-packed cloud (LDS.128).
// ============================================================================
#define QB 8
#define SUBS 16
#define TNB (QB * SUBS)   // 128 threads
#define TS 2048           // tile points (32KB smem)

__global__ __launch_bounds__(TNB, 4)
void nn_kernel()
{
    __shared__ float4 s_pts[TS];

    const int tid  = threadIdx.x;
    const int ql   = tid / SUBS;
    const int sub  = tid % SUBS;
    const int q    = blockIdx.x * QB + ql;      // 0 .. B*M-1
    const int b    = q / MM;

    const int fidx = g_fps[q];
    const float4* pc4b = g_pc4 + (size_t)b * NPTS;
    const float4 qp = pc4b[fidx];
    const float qx = qp.x, qy = qp.y, qz = qp.z;

    float d0 = finf(), d1 = finf(), d2 = finf();
    int   i0 = -1,     i1 = -1,     i2 = -1;

    for (int t0 = 0; t0 < NPTS; t0 += TS) {
        const int ts = min(TS, NPTS - t0);
        __syncthreads();
        for (int j = tid; j < ts; j += TNB)
            s_pts[j] = pc4b[t0 + j];
        __syncthreads();

        for (int j = sub; j < ts; j += SUBS) {
            float4 w = s_pts[j];
            float dx = w.x - qx;
            float dy = w.y - qy;
            float dz = w.z - qz;
            float d = fmaf(dz, dz, fmaf(dy, dy, dx * dx));
            if (d < d2) {
                int gi = t0 + j;
                if (d < d1) {
                    if (d < d0) { d2 = d1; i2 = i1; d1 = d0; i1 = i0; d0 = d; i0 = gi; }
                    else        { d2 = d1; i2 = i1; d1 = d;  i1 = gi; }
                } else          { d2 = d;  i2 = gi; }
            }
        }
    }

    // merge top-3 across the 16 lanes of this query
    #pragma unroll
    for (int off = SUBS / 2; off; off >>= 1) {
        float od0 = __shfl_down_sync(0xffffffffu, d0, off, SUBS);
        float od1 = __shfl_down_sync(0xffffffffu, d1, off, SUBS);
        float od2 = __shfl_down_sync(0xffffffffu, d2, off, SUBS);
        int   oi0 = __shfl_down_sync(0xffffffffu, i0, off, SUBS);
        int   oi1 = __shfl_down_sync(0xffffffffu, i1, off, SUBS);
        int   oi2 = __shfl_down_sync(0xffffffffu, i2, off, SUBS);
        #pragma unroll
        for (int k = 0; k < 3; ++k) {
            float d = (k == 0) ? od0 : (k == 1) ? od1 : od2;
            int   i = (k == 0) ? oi0 : (k == 1) ? oi1 : oi2;
            bool l2 = (d < d2) || (d == d2 && i < i2);
            if (l2) {
                bool l1 = (d < d1) || (d == d1 && i < i1);
                if (l1) {
                    bool l0 = (d < d0) || (d == d0 && i < i0);
                    if (l0) { d2 = d1; i2 = i1; d1 = d0; i1 = i0; d0 = d; i0 = i; }
                    else    { d2 = d1; i2 = i1; d1 = d;  i1 = i; }
                } else      { d2 = d;  i2 = i; }
            }
        }
    }

    if (sub == 0) {
        float e0 = sqrtf(fmaxf(d0, 0.0f));
        float e1 = sqrtf(fmaxf(d1, 0.0f));
        float e2 = sqrtf(fmaxf(d2, 0.0f));
        float w0 = 1.0f / (e0 + 1e-8f);
        float w1 = 1.0f / (e1 + 1e-8f);
        float w2 = 1.0f / (e2 + 1e-8f);
        float s  = __fadd_rn(__fadd_rn(w0, w1), w2);
        g_w[3 * q + 0] = w0 / s;
        g_w[3 * q + 1] = w1 / s;
        g_w[3 * q + 2] = w2 / s;
        g_nn[3 * q + 0] = i0;
        g_nn[3 * q + 1] = i1;
        g_nn[3 * q + 2] = i2;
    }
}

// ============================================================================
// Kernel 3: IDW feature interpolation. out[b,c,m] = sum_k w_k * feat[b,c,nn_k]
// ============================================================================
__global__ __launch_bounds__(256)
void interp_kernel(const float* __restrict__ feat, float* __restrict__ out)
{
    int e = blockIdx.x * blockDim.x + threadIdx.x;
    if (e >= BB * CC * MM) return;
    const int m = e % MM;
    const int c = (e / MM) % CC;
    const int b = e / (MM * CC);
    const int q = b * MM + m;

    const int   j0 = g_nn[3 * q],     j1 = g_nn[3 * q + 1], j2 = g_nn[3 * q + 2];
    const float w0 = g_w[3 * q],      w1 = g_w[3 * q + 1],  w2 = g_w[3 * q + 2];
    const float* f = feat + ((size_t)b * CC + c) * NPTS;
    out[e] = w0 * f[j0] + w1 * f[j1] + w2 * f[j2];
}

// ============================================================================
extern "C" void kernel_launch(void* const* d_in, const int* in_sizes, int n_in,
                              void* d_out, int out_size)
{
    const float* pc   = (const float*)d_in[0];  // (B,N,3)
    const float* feat = (const float*)d_in[1];  // (B,C,N)
    const float* obj  = (const float*)d_in[2];  // (B,2,N)
    const float* gr   = (const float*)d_in[3];  // (B,N)
    float* out = (float*)d_out;                 // (B,C,M)

    pack_kernel<<<(BB * NPTS + 255) / 256, 256>>>(pc);
    fps_kernel<<<BB * CLUSTER, FPS_T>>>(pc, obj, gr);
    nn_kernel<<<(BB * MM) / QB, TNB>>>();
    interp_kernel<<<(BB * CC * MM + 255) / 256, 256>>>(feat, out);
}

// round 5
// speedup vs baseline: 5.2843x; 5.2843x over previous
#include <cuda_runtime.h>
#include <cstdint>

#define BB 4
#define NPTS 20000
#define CC 512
#define MM 1024
#define GRASP_TH 0.1f

#define FPS_THREADS 512
#define FPS_WARPS (FPS_THREADS / 32)   // 16
#define CAPR 10                        // register-resident points per thread
#define PAIRS (CAPR / 2)               // 5 packed f32x2 pairs
#define REGN (FPS_THREADS * CAPR)      // 5120 register-resident points

// ---------------- scratch (static device allocations; no cudaMalloc) -------
__device__ float4 g_cp[BB * NPTS];    // compacted xyz
__device__ int    g_cidx[BB * NPTS];  // compacted -> original index
__device__ float  g_mind[BB * NPTS];  // FPS min-dist (gmem fallback region only)
__device__ int    g_fps[BB * MM];     // sampled original indices
__device__ int    g_nn[BB * MM * 3];  // 3-NN indices
__device__ float  g_w[BB * MM * 3];   // normalized IDW weights
__device__ float4 g_pc4[BB * NPTS];   // full cloud packed as float4

__device__ __forceinline__ float finf()  { return __int_as_float(0x7f800000); }

// packed f32x2 helpers (Blackwell sm_103a; per-component IEEE rn => bit-exact)
#define ADD2(out, a, b) asm("add.rn.f32x2 %0, %1, %2;" : "=l"(out) : "l"(a), "l"(b))
#define MUL2(out, a, b) asm("mul.rn.f32x2 %0, %1, %2;" : "=l"(out) : "l"(a), "l"(b))
#define PACK2(out, lo, hi) asm("mov.b64 %0, {%1, %2};" : "=l"(out) : "r"(lo), "r"(hi))
#define UNPACK2(lo, hi, in) asm("mov.b64 {%0, %1}, %2;" : "=r"(lo), "=r"(hi) : "l"(in))

// ============================================================================
// Kernel 0: pack full cloud into float4 for LDS.128 in nn_kernel
// ============================================================================
__global__ __launch_bounds__(256)
void pack_kernel(const float* __restrict__ pc)
{
    int e = blockIdx.x * 256 + threadIdx.x;
    if (e < BB * NPTS) {
        const float* p = pc + (size_t)e * 3;
        g_pc4[e] = make_float4(p[0], p[1], p[2], 0.0f);
    }
}

// ============================================================================
// Kernel 1: per-batch mask compaction + furthest point sampling.
// One block per batch; point state in registers, distances via packed f32x2
// (bit-exact: same per-component rn ops in the same ((dx2+dy2)+dz2) order).
// Argmax: strict > per lane (ascending index order) + REDUX max-value /
// min-index; winner coords re-fetched via broadcast L1 LDG.
// ============================================================================
__global__ __launch_bounds__(FPS_THREADS, 1)
void fps_kernel(const float* __restrict__ pc,
                const float* __restrict__ obj,
                const float* __restrict__ gr)
{
    const int b    = blockIdx.x;
    const int tid  = threadIdx.x;
    const int lane = tid & 31;
    const int wid  = tid >> 5;

    __shared__ int s_wsum[FPS_WARPS];
    __shared__ int s_base;
    __shared__ unsigned long long s_vi[2][FPS_WARPS];  // (valBits<<32) | ~idx

    if (tid == 0) s_base = 0;
    __syncthreads();

    const float* objb = obj + (size_t)b * 2 * NPTS;
    const float* grb  = gr  + (size_t)b * NPTS;
    const float* pcb  = pc  + (size_t)b * NPTS * 3;

    // ---- order-preserving compaction of masked points ----
    for (int start = 0; start < NPTS; start += FPS_THREADS) {
        int i = start + tid;
        bool p = false;
        if (i < NPTS)
            p = (objb[NPTS + i] > objb[i]) && (grb[i] > GRASP_TH);
        unsigned bal = __ballot_sync(0xffffffffu, p);
        int wcnt = __popc(bal);
        int wpre = __popc(bal & ((1u << lane) - 1u));
        if (lane == 0) s_wsum[wid] = wcnt;
        __syncthreads();
        if (tid == 0) {
            int acc = s_base;
            #pragma unroll
            for (int w = 0; w < FPS_WARPS; ++w) { int c = s_wsum[w]; s_wsum[w] = acc; acc += c; }
            s_base = acc;
        }
        __syncthreads();
        if (p) {
            int pos = s_wsum[wid] + wpre;
            g_cidx[b * NPTS + pos] = i;
            float4 q;
            q.x = pcb[3 * i]; q.y = pcb[3 * i + 1]; q.z = pcb[3 * i + 2]; q.w = 0.0f;
            g_cp[b * NPTS + pos] = q;
        }
        __syncthreads();
    }
    const int cnt = s_base;

    if (cnt == 0) {
        for (int j = tid; j < MM; j += FPS_THREADS) g_fps[b * MM + j] = 0;
        return;
    }

    const float4* cp = g_cp + b * NPTS;
    const int regCnt = min(cnt, REGN);

    // ---- load owned points into packed registers ----
    unsigned long long rx2[PAIRS], ry2[PAIRS], rz2[PAIRS];
    float md[CAPR];
    #pragma unroll
    for (int p = 0; p < PAIRS; ++p) {
        const int k0 = 2 * p, k1 = 2 * p + 1;
        int i0 = tid + k0 * FPS_THREADS;
        int i1 = tid + k1 * FPS_THREADS;
        float x0 = 0.f, y0 = 0.f, z0 = 0.f, x1 = 0.f, y1 = 0.f, z1 = 0.f;
        if (i0 < regCnt) { float4 q = cp[i0]; x0 = q.x; y0 = q.y; z0 = q.z; md[k0] = finf(); }
        else               md[k0] = -0.0f;   // -0: fmin keeps -0, never beats bV>=0 under strict >
        if (i1 < regCnt) { float4 q = cp[i1]; x1 = q.x; y1 = q.y; z1 = q.z; md[k1] = finf(); }
        else               md[k1] = -0.0f;
        PACK2(rx2[p], __float_as_uint(x0), __float_as_uint(x1));
        PACK2(ry2[p], __float_as_uint(y0), __float_as_uint(y1));
        PACK2(rz2[p], __float_as_uint(z0), __float_as_uint(z1));
    }

    // fallback region (cnt > 5120): gmem state
    float* gmind = g_mind + b * NPTS;
    for (int i = REGN + tid; i < cnt; i += FPS_THREADS) gmind[i] = finf();
    __syncthreads();

    // ---- first pick = compacted point 0 ----
    float4 p0 = cp[0];
    float lx = p0.x, ly = p0.y, lz = p0.z;
    if (tid == 0) g_fps[b * MM] = g_cidx[b * NPTS];

    for (int it = 1; it < MM; ++it) {
        const unsigned ph = (unsigned)(it - 1) & 1u;

        unsigned long long nlx2, nly2, nlz2;
        {
            unsigned nx = __float_as_uint(-lx);
            unsigned ny = __float_as_uint(-ly);
            unsigned nz = __float_as_uint(-lz);
            PACK2(nlx2, nx, nx);
            PACK2(nly2, ny, ny);
            PACK2(nlz2, nz, nz);
        }

        float    bV = 0.0f;              // sentinel: all-zero case handled at the end
        unsigned bI = 0xffffffffu;
        #pragma unroll
        for (int p = 0; p < PAIRS; ++p) {
            unsigned long long dx2, dy2, dz2, s2;
            ADD2(dx2, rx2[p], nlx2);     // dx = rx - lx (exact rn)
            MUL2(dx2, dx2, dx2);         // dx*dx
            ADD2(dy2, ry2[p], nly2);
            MUL2(dy2, dy2, dy2);
            ADD2(s2, dx2, dy2);          // dx*dx + dy*dy
            ADD2(dz2, rz2[p], nlz2);
            MUL2(dz2, dz2, dz2);
            ADD2(s2, s2, dz2);           // (dx*dx + dy*dy) + dz*dz  -- XLA order
            unsigned dlo, dhi;
            UNPACK2(dlo, dhi, s2);
            float m0 = fminf(md[2 * p],     __uint_as_float(dlo));
            float m1 = fminf(md[2 * p + 1], __uint_as_float(dhi));
            md[2 * p]     = m0;
            md[2 * p + 1] = m1;
            if (m0 > bV) { bV = m0; bI = (unsigned)(tid + (2 * p)     * FPS_THREADS); }
            if (m1 > bV) { bV = m1; bI = (unsigned)(tid + (2 * p + 1) * FPS_THREADS); }
        }
        // fallback region (usually empty)
        for (int i = REGN + tid; i < cnt; i += FPS_THREADS) {
            float4 q = cp[i];
            float dx = q.x - lx;
            float dy = q.y - ly;
            float dz = q.z - lz;
            float d = __fadd_rn(__fadd_rn(__fmul_rn(dx, dx),
                                          __fmul_rn(dy, dy)),
                                __fmul_rn(dz, dz));
            float m = fminf(gmind[i], d);
            gmind[i] = m;
            if (m > bV || (m == bV && (unsigned)i < bI)) { bV = m; bI = (unsigned)i; }
        }

        // --- warp argmax via REDUX (bV >= 0 => f32 bits are u32-monotone) ---
        unsigned vb = __float_as_uint(bV);
        unsigned wv = __reduce_max_sync(0xffffffffu, vb);
        unsigned cand = (vb == wv) ? bI : 0xffffffffu;
        unsigned wi = __reduce_min_sync(0xffffffffu, cand);
        if (vb == wv && bI == wi)        // winning lane(s) write identical value
            s_vi[ph][wid] = ((unsigned long long)wv << 32) | (unsigned)(~wi);
        __syncthreads();

        // --- cross-warp argmax over 16 entries, redundantly in every warp ---
        unsigned long long e = s_vi[ph][lane & (FPS_WARPS - 1)];
        unsigned hv = (unsigned)(e >> 32);
        unsigned lv = (unsigned)e;                  // = ~idx
        unsigned gv = __reduce_max_sync(0xffffffffu, hv);
        unsigned cl = (hv == gv) ? lv : 0u;         // max ~idx == min idx
        unsigned gl = __reduce_max_sync(0xffffffffu, cl);
        unsigned gi = ~gl;
        if (gv == 0u) gi = 0u;   // degenerate: all minds zero -> first masked point

        // --- fetch winner coords: broadcast LDG, L1-resident ---
        float4 w = cp[gi];
        lx = w.x; ly = w.y; lz = w.z;

        if (tid == 0) g_fps[b * MM + it] = g_cidx[b * NPTS + (int)gi];
    }
}

// ============================================================================
// Kernel 2: three_nn — tiled brute force over float4-packed cloud (LDS.128).
// ============================================================================
#define QB 8
#define SUBS 16
#define TNB (QB * SUBS)   // 128 threads
#define TS 2048           // tile points (32KB smem)

__global__ __launch_bounds__(TNB, 4)
void nn_kernel()
{
    __shared__ float4 s_pts[TS];

    const int tid  = threadIdx.x;
    const int ql   = tid / SUBS;
    const int sub  = tid % SUBS;
    const int q    = blockIdx.x * QB + ql;      // 0 .. B*M-1
    const int b    = q / MM;

    const int fidx = g_fps[q];
    const float4* pc4b = g_pc4 + (size_t)b * NPTS;
    const float4 qp = pc4b[fidx];
    const float qx = qp.x, qy = qp.y, qz = qp.z;

    float d0 = finf(), d1 = finf(), d2 = finf();
    int   i0 = -1,     i1 = -1,     i2 = -1;

    for (int t0 = 0; t0 < NPTS; t0 += TS) {
        const int ts = min(TS, NPTS - t0);
        __syncthreads();
        for (int j = tid; j < ts; j += TNB)
            s_pts[j] = pc4b[t0 + j];
        __syncthreads();

        for (int j = sub; j < ts; j += SUBS) {
            float4 w = s_pts[j];
            float dx = w.x - qx;
            float dy = w.y - qy;
            float dz = w.z - qz;
            float d = fmaf(dz, dz, fmaf(dy, dy, dx * dx));
            if (d < d2) {
                int gi = t0 + j;
                if (d < d1) {
                    if (d < d0) { d2 = d1; i2 = i1; d1 = d0; i1 = i0; d0 = d; i0 = gi; }
                    else        { d2 = d1; i2 = i1; d1 = d;  i1 = gi; }
                } else          { d2 = d;  i2 = gi; }
            }
        }
    }

    // merge top-3 across the 16 lanes of this query
    #pragma unroll
    for (int off = SUBS / 2; off; off >>= 1) {
        float od0 = __shfl_down_sync(0xffffffffu, d0, off, SUBS);
        float od1 = __shfl_down_sync(0xffffffffu, d1, off, SUBS);
        float od2 = __shfl_down_sync(0xffffffffu, d2, off, SUBS);
        int   oi0 = __shfl_down_sync(0xffffffffu, i0, off, SUBS);
        int   oi1 = __shfl_down_sync(0xffffffffu, i1, off, SUBS);
        int   oi2 = __shfl_down_sync(0xffffffffu, i2, off, SUBS);
        #pragma unroll
        for (int k = 0; k < 3; ++k) {
            float d = (k == 0) ? od0 : (k == 1) ? od1 : od2;
            int   i = (k == 0) ? oi0 : (k == 1) ? oi1 : oi2;
            bool l2 = (d < d2) || (d == d2 && i < i2);
            if (l2) {
                bool l1 = (d < d1) || (d == d1 && i < i1);
                if (l1) {
                    bool l0 = (d < d0) || (d == d0 && i < i0);
                    if (l0) { d2 = d1; i2 = i1; d1 = d0; i1 = i0; d0 = d; i0 = i; }
                    else    { d2 = d1; i2 = i1; d1 = d;  i1 = i; }
                } else      { d2 = d;  i2 = i; }
            }
        }
    }

    if (sub == 0) {
        float e0 = sqrtf(fmaxf(d0, 0.0f));
        float e1 = sqrtf(fmaxf(d1, 0.0f));
        float e2 = sqrtf(fmaxf(d2, 0.0f));
        float w0 = 1.0f / (e0 + 1e-8f);
        float w1 = 1.0f / (e1 + 1e-8f);
        float w2 = 1.0f / (e2 + 1e-8f);
        float s  = __fadd_rn(__fadd_rn(w0, w1), w2);
        g_w[3 * q + 0] = w0 / s;
        g_w[3 * q + 1] = w1 / s;
        g_w[3 * q + 2] = w2 / s;
        g_nn[3 * q + 0] = i0;
        g_nn[3 * q + 1] = i1;
        g_nn[3 * q + 2] = i2;
    }
}

// ============================================================================
// Kernel 3: IDW feature interpolation. out[b,c,m] = sum_k w_k * feat[b,c,nn_k]
// ============================================================================
__global__ __launch_bounds__(256)
void interp_kernel(const float* __restrict__ feat, float* __restrict__ out)
{
    int e = blockIdx.x * blockDim.x + threadIdx.x;
    if (e >= BB * CC * MM) return;
    const int m = e % MM;
    const int c = (e / MM) % CC;
    const int b = e / (MM * CC);
    const int q = b * MM + m;

    const int   j0 = g_nn[3 * q],     j1 = g_nn[3 * q + 1], j2 = g_nn[3 * q + 2];
    const float w0 = g_w[3 * q],      w1 = g_w[3 * q + 1],  w2 = g_w[3 * q + 2];
    const float* f = feat + ((size_t)b * CC + c) * NPTS;
    out[e] = w0 * f[j0] + w1 * f[j1] + w2 * f[j2];
}

// ============================================================================
extern "C" void kernel_launch(void* const* d_in, const int* in_sizes, int n_in,
                              void* d_out, int out_size)
{
    const float* pc   = (const float*)d_in[0];  // (B,N,3)
    const float* feat = (const float*)d_in[1];  // (B,C,N)
    const float* obj  = (const float*)d_in[2];  // (B,2,N)
    const float* gr   = (const float*)d_in[3];  // (B,N)
    float* out = (float*)d_out;                 // (B,C,M)

    pack_kernel<<<(BB * NPTS + 255) / 256, 256>>>(pc);
    fps_kernel<<<BB, FPS_THREADS>>>(pc, obj, gr);
    nn_kernel<<<(BB * MM) / QB, TNB>>>();
    interp_kernel<<<(BB * CC * MM + 255) / 256, 256>>>(feat, out);
}

// round 6
// speedup vs baseline: 5.2965x; 1.0023x over previous
#include <cuda_runtime.h>
#include <cstdint>

#define BB 4
#define NPTS 20000
#define CC 512
#define MM 1024
#define GRASP_TH 0.1f

#define FPS_THREADS 512
#define FPS_WARPS (FPS_THREADS / 32)   // 16
#define CAPR 10                        // register-resident points per thread
#define PAIRS (CAPR / 2)               // 5 packed f32x2 pairs
#define REGN (FPS_THREADS * CAPR)      // 5120 register-resident points

// ---------------- scratch (static device allocations; no cudaMalloc) -------
__device__ float4 g_cp[BB * NPTS];    // compacted xyz
__device__ int    g_cidx[BB * NPTS];  // compacted -> original index
__device__ float  g_mind[BB * NPTS];  // FPS min-dist (gmem fallback region only)
__device__ int    g_fps[BB * MM];     // sampled original indices
__device__ int    g_nn[BB * MM * 3];  // 3-NN indices
__device__ float  g_w[BB * MM * 3];   // normalized IDW weights
__device__ float4 g_pc4[BB * NPTS];   // full cloud packed as float4

__device__ __forceinline__ float finf()  { return __int_as_float(0x7f800000); }

// packed f32x2 helpers (Blackwell sm_103a; per-component IEEE rn => bit-exact)
#define ADD2(out, a, b) asm("add.rn.f32x2 %0, %1, %2;" : "=l"(out) : "l"(a), "l"(b))
#define MUL2(out, a, b) asm("mul.rn.f32x2 %0, %1, %2;" : "=l"(out) : "l"(a), "l"(b))
#define PACK2(out, lo, hi) asm("mov.b64 %0, {%1, %2};" : "=l"(out) : "r"(lo), "r"(hi))
#define UNPACK2(lo, hi, in) asm("mov.b64 {%0, %1}, %2;" : "=r"(lo), "=r"(hi) : "l"(in))

// ============================================================================
// Kernel 0: pack full cloud into float4 for LDS.128 in nn_kernel
// ============================================================================
__global__ __launch_bounds__(256)
void pack_kernel(const float* __restrict__ pc)
{
    int e = blockIdx.x * 256 + threadIdx.x;
    if (e < BB * NPTS) {
        const float* p = pc + (size_t)e * 3;
        g_pc4[e] = make_float4(p[0], p[1], p[2], 0.0f);
    }
}

// ============================================================================
// Kernel 1: per-batch mask compaction + furthest point sampling.
// (unchanged from R5 — passing & bit-exact; fma/latency bound on 4 SMs)
// ============================================================================
__global__ __launch_bounds__(FPS_THREADS, 1)
void fps_kernel(const float* __restrict__ pc,
                const float* __restrict__ obj,
                const float* __restrict__ gr)
{
    const int b    = blockIdx.x;
    const int tid  = threadIdx.x;
    const int lane = tid & 31;
    const int wid  = tid >> 5;

    __shared__ int s_wsum[FPS_WARPS];
    __shared__ int s_base;
    __shared__ unsigned long long s_vi[2][FPS_WARPS];  // (valBits<<32) | ~idx

    if (tid == 0) s_base = 0;
    __syncthreads();

    const float* objb = obj + (size_t)b * 2 * NPTS;
    const float* grb  = gr  + (size_t)b * NPTS;
    const float* pcb  = pc  + (size_t)b * NPTS * 3;

    // ---- order-preserving compaction of masked points ----
    for (int start = 0; start < NPTS; start += FPS_THREADS) {
        int i = start + tid;
        bool p = false;
        if (i < NPTS)
            p = (objb[NPTS + i] > objb[i]) && (grb[i] > GRASP_TH);
        unsigned bal = __ballot_sync(0xffffffffu, p);
        int wcnt = __popc(bal);
        int wpre = __popc(bal & ((1u << lane) - 1u));
        if (lane == 0) s_wsum[wid] = wcnt;
        __syncthreads();
        if (tid == 0) {
            int acc = s_base;
            #pragma unroll
            for (int w = 0; w < FPS_WARPS; ++w) { int c = s_wsum[w]; s_wsum[w] = acc; acc += c; }
            s_base = acc;
        }
        __syncthreads();
        if (p) {
            int pos = s_wsum[wid] + wpre;
            g_cidx[b * NPTS + pos] = i;
            float4 q;
            q.x = pcb[3 * i]; q.y = pcb[3 * i + 1]; q.z = pcb[3 * i + 2]; q.w = 0.0f;
            g_cp[b * NPTS + pos] = q;
        }
        __syncthreads();
    }
    const int cnt = s_base;

    if (cnt == 0) {
        for (int j = tid; j < MM; j += FPS_THREADS) g_fps[b * MM + j] = 0;
        return;
    }

    const float4* cp = g_cp + b * NPTS;
    const int regCnt = min(cnt, REGN);

    // ---- load owned points into packed registers ----
    unsigned long long rx2[PAIRS], ry2[PAIRS], rz2[PAIRS];
    float md[CAPR];
    #pragma unroll
    for (int p = 0; p < PAIRS; ++p) {
        const int k0 = 2 * p, k1 = 2 * p + 1;
        int i0 = tid + k0 * FPS_THREADS;
        int i1 = tid + k1 * FPS_THREADS;
        float x0 = 0.f, y0 = 0.f, z0 = 0.f, x1 = 0.f, y1 = 0.f, z1 = 0.f;
        if (i0 < regCnt) { float4 q = cp[i0]; x0 = q.x; y0 = q.y; z0 = q.z; md[k0] = finf(); }
        else               md[k0] = -0.0f;   // -0: never beats bV>=0 under strict >
        if (i1 < regCnt) { float4 q = cp[i1]; x1 = q.x; y1 = q.y; z1 = q.z; md[k1] = finf(); }
        else               md[k1] = -0.0f;
        PACK2(rx2[p], __float_as_uint(x0), __float_as_uint(x1));
        PACK2(ry2[p], __float_as_uint(y0), __float_as_uint(y1));
        PACK2(rz2[p], __float_as_uint(z0), __float_as_uint(z1));
    }

    // fallback region (cnt > 5120): gmem state
    float* gmind = g_mind + b * NPTS;
    for (int i = REGN + tid; i < cnt; i += FPS_THREADS) gmind[i] = finf();
    __syncthreads();

    // ---- first pick = compacted point 0 ----
    float4 p0 = cp[0];
    float lx = p0.x, ly = p0.y, lz = p0.z;
    if (tid == 0) g_fps[b * MM] = g_cidx[b * NPTS];

    for (int it = 1; it < MM; ++it) {
        const unsigned ph = (unsigned)(it - 1) & 1u;

        unsigned long long nlx2, nly2, nlz2;
        {
            unsigned nx = __float_as_uint(-lx);
            unsigned ny = __float_as_uint(-ly);
            unsigned nz = __float_as_uint(-lz);
            PACK2(nlx2, nx, nx);
            PACK2(nly2, ny, ny);
            PACK2(nlz2, nz, nz);
        }

        float    bV = 0.0f;
        unsigned bI = 0xffffffffu;
        #pragma unroll
        for (int p = 0; p < PAIRS; ++p) {
            unsigned long long dx2, dy2, dz2, s2;
            ADD2(dx2, rx2[p], nlx2);     // dx = rx - lx (exact rn)
            MUL2(dx2, dx2, dx2);
            ADD2(dy2, ry2[p], nly2);
            MUL2(dy2, dy2, dy2);
            ADD2(s2, dx2, dy2);
            ADD2(dz2, rz2[p], nlz2);
            MUL2(dz2, dz2, dz2);
            ADD2(s2, s2, dz2);           // (dx*dx + dy*dy) + dz*dz  -- XLA order
            unsigned dlo, dhi;
            UNPACK2(dlo, dhi, s2);
            float m0 = fminf(md[2 * p],     __uint_as_float(dlo));
            float m1 = fminf(md[2 * p + 1], __uint_as_float(dhi));
            md[2 * p]     = m0;
            md[2 * p + 1] = m1;
            if (m0 > bV) { bV = m0; bI = (unsigned)(tid + (2 * p)     * FPS_THREADS); }
            if (m1 > bV) { bV = m1; bI = (unsigned)(tid + (2 * p + 1) * FPS_THREADS); }
        }
        for (int i = REGN + tid; i < cnt; i += FPS_THREADS) {
            float4 q = cp[i];
            float dx = q.x - lx;
            float dy = q.y - ly;
            float dz = q.z - lz;
            float d = __fadd_rn(__fadd_rn(__fmul_rn(dx, dx),
                                          __fmul_rn(dy, dy)),
                                __fmul_rn(dz, dz));
            float m = fminf(gmind[i], d);
            gmind[i] = m;
            if (m > bV || (m == bV && (unsigned)i < bI)) { bV = m; bI = (unsigned)i; }
        }

        // --- warp argmax via REDUX (bV >= 0 => f32 bits are u32-monotone) ---
        unsigned vb = __float_as_uint(bV);
        unsigned wv = __reduce_max_sync(0xffffffffu, vb);
        unsigned cand = (vb == wv) ? bI : 0xffffffffu;
        unsigned wi = __reduce_min_sync(0xffffffffu, cand);
        if (vb == wv && bI == wi)
            s_vi[ph][wid] = ((unsigned long long)wv << 32) | (unsigned)(~wi);
        __syncthreads();

        // --- cross-warp argmax over 16 entries, redundantly in every warp ---
        unsigned long long e = s_vi[ph][lane & (FPS_WARPS - 1)];
        unsigned hv = (unsigned)(e >> 32);
        unsigned lv = (unsigned)e;                  // = ~idx
        unsigned gv = __reduce_max_sync(0xffffffffu, hv);
        unsigned cl = (hv == gv) ? lv : 0u;         // max ~idx == min idx
        unsigned gl = __reduce_max_sync(0xffffffffu, cl);
        unsigned gi = ~gl;
        if (gv == 0u) gi = 0u;   // degenerate: all minds zero -> first masked point

        // --- fetch winner coords: broadcast LDG, L1-resident ---
        float4 w = cp[gi];
        lx = w.x; ly = w.y; lz = w.z;

        if (tid == 0) g_fps[b * MM + it] = g_cidx[b * NPTS + (int)gi];
    }
}

// ============================================================================
// Kernel 2: three_nn — warp serves 4 queries; each lane loads each tile point
// ONCE (LDS.128) and updates 4 register top-3s. Block = 256 thr (8 warps,
// 32 queries), grid = 128 blocks (batch-aligned, one wave).
// ============================================================================
#define NNQ 4              // queries per warp
#define NNT 256            // threads per block
#define NNW (NNT / 32)     // 8 warps
#define QPB (NNW * NNQ)    // 32 queries per block
#define NTS 2048           // tile points (32KB smem)

__global__ __launch_bounds__(NNT, 1)
void nn_kernel()
{
    __shared__ float4 s_pts[NTS];

    const int tid  = threadIdx.x;
    const int lane = tid & 31;
    const int wid  = tid >> 5;
    const int b    = blockIdx.x / (MM / QPB);       // 32 blocks per batch
    const int q0   = blockIdx.x * QPB + wid * NNQ;  // first of my 4 queries

    const float4* pc4b = g_pc4 + (size_t)b * NPTS;

    float qx[NNQ], qy[NNQ], qz[NNQ];
    #pragma unroll
    for (int t = 0; t < NNQ; ++t) {
        const float4 qp = pc4b[g_fps[q0 + t]];
        qx[t] = qp.x; qy[t] = qp.y; qz[t] = qp.z;
    }

    float d0[NNQ], d1[NNQ], d2[NNQ];
    int   i0[NNQ], i1[NNQ], i2[NNQ];
    #pragma unroll
    for (int t = 0; t < NNQ; ++t) {
        d0[t] = finf(); d1[t] = finf(); d2[t] = finf();
        i0[t] = -1;     i1[t] = -1;     i2[t] = -1;
    }

    for (int t0 = 0; t0 < NPTS; t0 += NTS) {
        const int ts = min(NTS, NPTS - t0);
        __syncthreads();
        for (int j = tid; j < ts; j += NNT)
            s_pts[j] = pc4b[t0 + j];
        __syncthreads();

        for (int j = lane; j < ts; j += 32) {
            const float4 w = s_pts[j];
            const int gi = t0 + j;
            #pragma unroll
            for (int t = 0; t < NNQ; ++t) {
                float dx = w.x - qx[t];
                float dy = w.y - qy[t];
                float dz = w.z - qz[t];
                float d = fmaf(dz, dz, fmaf(dy, dy, dx * dx));
                if (d < d2[t]) {
                    if (d < d1[t]) {
                        if (d < d0[t]) { d2[t] = d1[t]; i2[t] = i1[t];
                                         d1[t] = d0[t]; i1[t] = i0[t];
                                         d0[t] = d;     i0[t] = gi; }
                        else           { d2[t] = d1[t]; i2[t] = i1[t];
                                         d1[t] = d;     i1[t] = gi; }
                    } else             { d2[t] = d;     i2[t] = gi; }
                }
            }
        }
    }

    // merge top-3 across the 32 lanes, per query (tie-break: d asc, idx asc)
    #pragma unroll
    for (int t = 0; t < NNQ; ++t) {
        #pragma unroll
        for (int off = 16; off; off >>= 1) {
            float od0 = __shfl_down_sync(0xffffffffu, d0[t], off);
            float od1 = __shfl_down_sync(0xffffffffu, d1[t], off);
            float od2 = __shfl_down_sync(0xffffffffu, d2[t], off);
            int   oi0 = __shfl_down_sync(0xffffffffu, i0[t], off);
            int   oi1 = __shfl_down_sync(0xffffffffu, i1[t], off);
            int   oi2 = __shfl_down_sync(0xffffffffu, i2[t], off);
            #pragma unroll
            for (int k = 0; k < 3; ++k) {
                float d = (k == 0) ? od0 : (k == 1) ? od1 : od2;
                int   i = (k == 0) ? oi0 : (k == 1) ? oi1 : oi2;
                bool l2 = (d < d2[t]) || (d == d2[t] && i < i2[t]);
                if (l2) {
                    bool l1 = (d < d1[t]) || (d == d1[t] && i < i1[t]);
                    if (l1) {
                        bool l0 = (d < d0[t]) || (d == d0[t] && i < i0[t]);
                        if (l0) { d2[t] = d1[t]; i2[t] = i1[t];
                                  d1[t] = d0[t]; i1[t] = i0[t];
                                  d0[t] = d;     i0[t] = i; }
                        else    { d2[t] = d1[t]; i2[t] = i1[t];
                                  d1[t] = d;     i1[t] = i; }
                    } else      { d2[t] = d;     i2[t] = i; }
                }
            }
        }
        if (lane == 0) {
            const int q = q0 + t;
            float e0 = sqrtf(fmaxf(d0[t], 0.0f));
            float e1 = sqrtf(fmaxf(d1[t], 0.0f));
            float e2 = sqrtf(fmaxf(d2[t], 0.0f));
            float w0 = 1.0f / (e0 + 1e-8f);
            float w1 = 1.0f / (e1 + 1e-8f);
            float w2 = 1.0f / (e2 + 1e-8f);
            float s  = __fadd_rn(__fadd_rn(w0, w1), w2);
            g_w[3 * q + 0] = w0 / s;
            g_w[3 * q + 1] = w1 / s;
            g_w[3 * q + 2] = w2 / s;
            g_nn[3 * q + 0] = i0[t];
            g_nn[3 * q + 1] = i1[t];
            g_nn[3 * q + 2] = i2[t];
        }
    }
}

// ============================================================================
// Kernel 3: IDW feature interpolation. out[b,c,m] = sum_k w_k * feat[b,c,nn_k]
// ============================================================================
__global__ __launch_bounds__(256)
void interp_kernel(const float* __restrict__ feat, float* __restrict__ out)
{
    int e = blockIdx.x * blockDim.x + threadIdx.x;
    if (e >= BB * CC * MM) return;
    const int m = e % MM;
    const int c = (e / MM) % CC;
    const int b = e / (MM * CC);
    const int q = b * MM + m;

    const int   j0 = g_nn[3 * q],     j1 = g_nn[3 * q + 1], j2 = g_nn[3 * q + 2];
    const float w0 = g_w[3 * q],      w1 = g_w[3 * q + 1],  w2 = g_w[3 * q + 2];
    const float* f = feat + ((size_t)b * CC + c) * NPTS;
    out[e] = w0 * f[j0] + w1 * f[j1] + w2 * f[j2];
}

// ============================================================================
extern "C" void kernel_launch(void* const* d_in, const int* in_sizes, int n_in,
                              void* d_out, int out_size)
{
    const float* pc   = (const float*)d_in[0];  // (B,N,3)
    const float* feat = (const float*)d_in[1];  // (B,C,N)
    const float* obj  = (const float*)d_in[2];  // (B,2,N)
    const float* gr   = (const float*)d_in[3];  // (B,N)
    float* out = (float*)d_out;                 // (B,C,M)

    pack_kernel<<<(BB * NPTS + 255) / 256, 256>>>(pc);
    fps_kernel<<<BB, FPS_THREADS>>>(pc, obj, gr);
    nn_kernel<<<(BB * MM) / QPB, NNT>>>();
    interp_kernel<<<(BB * CC * MM + 255) / 256, 256>>>(feat, out);
}